// round 1
// baseline (speedup 1.0000x reference)
#include <cuda_runtime.h>
#include <cuda_bf16.h>

#define NG 10000
#define W 256
#define H 256
#define TILE 16
#define NCHUNK 256

// Preprocessed gaussian data (static device scratch; no dynamic alloc)
static __device__ float4 g_bbox[NG];  // cx, cy, rx, ry   (rx<0 => culled)
static __device__ float4 g_parA[NG];  // 0.5*conic_a, conic_b, 0.5*conic_c, op
static __device__ float4 g_parB[NG];  // r, g, b, pad

__global__ void prep_kernel(const float* __restrict__ xyz,
                            const float* __restrict__ chol,
                            const float* __restrict__ colors,
                            const float* __restrict__ opacity) {
    int i = blockIdx.x * blockDim.x + threadIdx.x;
    if (i >= NG) return;
    float mx = tanhf(xyz[2 * i]);
    float my = tanhf(xyz[2 * i + 1]);
    float cx = 0.5f * W * (mx + 1.0f);
    float cy = 0.5f * H * (my + 1.0f);
    float L0 = chol[3 * i] + 0.5f;
    float L1 = chol[3 * i + 1] + 0.0f;
    float L2 = chol[3 * i + 2] + 0.5f;
    float cxx = L0 * L0;
    float cxy = L0 * L1;
    float cyy = L1 * L1 + L2 * L2;
    float det = cxx * cyy - cxy * cxy;
    float ca = cyy / det;
    float cb = -cxy / det;
    float cc = cxx / det;
    float op = opacity[i];
    // alpha = op*exp(-sigma) >= 1/255  <=>  sigma <= log(255*op)
    float T = logf(255.0f * op) + 0.05f;  // small margin for fp slop
    float rx = -1.0f, ry = -1.0f;
    if (det > 0.0f && op > 0.0f && T > 0.0f) {
        // level set sigma = T has |dx|max = sqrt(2*T*cov_xx), |dy|max = sqrt(2*T*cov_yy)
        rx = sqrtf(2.0f * T * cxx) + 1.0f;
        ry = sqrtf(2.0f * T * cyy) + 1.0f;
    }
    g_bbox[i] = make_float4(cx, cy, rx, ry);
    g_parA[i] = make_float4(0.5f * ca, cb, 0.5f * cc, op);
    g_parB[i] = make_float4(colors[3 * i], colors[3 * i + 1], colors[3 * i + 2], 0.0f);
}

__global__ __launch_bounds__(256) void render_kernel(
    const float* __restrict__ scale_f,
    const float* __restrict__ shift_f,
    float* __restrict__ out) {
    __shared__ float4 sA[NCHUNK];  // cx, cy, 0.5a, b
    __shared__ float4 sB[NCHUNK];  // 0.5c, op, colR, colG
    __shared__ float  sC[NCHUNK];  // colB
    __shared__ int    wcnt[8];

    const int tid  = threadIdx.x;
    const int lane = tid & 31;
    const int wid  = tid >> 5;
    const int lx = tid & (TILE - 1);
    const int ly = tid >> 4;
    const int px = blockIdx.x * TILE + lx;
    const int py = blockIdx.y * TILE + ly;
    const float fpx = (float)px;
    const float fpy = (float)py;
    const float x0 = (float)(blockIdx.x * TILE);
    const float x1 = x0 + (float)(TILE - 1);
    const float y0 = (float)(blockIdx.y * TILE);
    const float y1 = y0 + (float)(TILE - 1);

    float accR = 0.0f, accG = 0.0f, accB = 0.0f;

    for (int base = 0; base < NG; base += NCHUNK) {
        int g = base + tid;
        bool pass = false;
        float4 bb = make_float4(0.f, 0.f, 0.f, 0.f);
        if (g < NG) {
            bb = g_bbox[g];
            pass = (bb.z >= 0.0f) &&
                   (bb.x + bb.z >= x0) && (bb.x - bb.z <= x1) &&
                   (bb.y + bb.w >= y0) && (bb.y - bb.w <= y1);
        }
        unsigned ball = __ballot_sync(0xffffffffu, pass);
        if (lane == 0) wcnt[wid] = __popc(ball);
        __syncthreads();
        // deterministic exclusive prefix over the 8 warps
        int off = 0, cnt = 0;
        #pragma unroll
        for (int k = 0; k < 8; k++) {
            int c = wcnt[k];
            if (k < wid) off += c;
            cnt += c;
        }
        if (pass) {
            int pos = off + __popc(ball & ((1u << lane) - 1u));
            float4 pA = g_parA[g];
            float4 pB = g_parB[g];
            sA[pos] = make_float4(bb.x, bb.y, pA.x, pA.y);
            sB[pos] = make_float4(pA.z, pA.w, pB.x, pB.y);
            sC[pos] = pB.z;
        }
        __syncthreads();

        for (int j = 0; j < cnt; j++) {
            float4 A = sA[j];
            float4 B = sB[j];
            float dx = A.x - fpx;
            float dy = A.y - fpy;
            // sigma = 0.5*a*dx^2 + 0.5*c*dy^2 + b*dx*dy
            float sig = fmaf(A.z * dx, dx, fmaf(B.x * dy, dy, A.w * (dx * dy)));
            float alpha = B.y * __expf(-sig);
            bool ok = (sig >= 0.0f) && (alpha >= (1.0f / 255.0f));
            float w = ok ? fminf(alpha, 0.999f) : 0.0f;
            accR = fmaf(w, B.z, accR);
            accG = fmaf(w, B.w, accG);
            accB = fmaf(w, sC[j], accB);
        }
        __syncthreads();
    }

    float s  = scale_f[0];
    float sh = shift_f[0];
    int idx = py * W + px;
    out[0 * (H * W) + idx] = fmaf(accR, s, sh);
    out[1 * (H * W) + idx] = fmaf(accG, s, sh);
    out[2 * (H * W) + idx] = fmaf(accB, s, sh);
}

extern "C" void kernel_launch(void* const* d_in, const int* in_sizes, int n_in,
                              void* d_out, int out_size) {
    const float* xyz     = (const float*)d_in[0];
    const float* chol    = (const float*)d_in[1];
    const float* colors  = (const float*)d_in[2];
    const float* opacity = (const float*)d_in[3];
    const float* scale_f = (const float*)d_in[4];
    const float* shift_f = (const float*)d_in[5];
    float* out = (float*)d_out;

    prep_kernel<<<(NG + 255) / 256, 256>>>(xyz, chol, colors, opacity);
    dim3 grid(W / TILE, H / TILE);
    render_kernel<<<grid, 256>>>(scale_f, shift_f, out);
}

// round 2
// speedup vs baseline: 1.1632x; 1.1632x over previous
#include <cuda_runtime.h>
#include <cuda_bf16.h>

#define NG 10000
#define W 256
#define H 256
#define TS 16    // tile size in pixels
#define TX 16    // tiles per image row
#define TY 16    // tile rows

// Static device scratch (no dynamic alloc allowed)
static __device__ float4 g_parA[NG];        // cx, cy, ha*log2e, b*log2e
static __device__ float4 g_parB[NG];        // hc*log2e, log2(op), colR, colG
static __device__ float  g_parC[NG];        // colB
static __device__ int    g_rng[NG];         // packed tx0|tx1<<4|ty0<<8|ty1<<12
static __device__ int    g_rowlist[TY * NG];// per-row gid lists (entry: gid | tx0<<20 | tx1<<24)
static __device__ int    g_rowcnt[TY];

__global__ void prep_kernel(const float* __restrict__ xyz,
                            const float* __restrict__ chol,
                            const float* __restrict__ colors,
                            const float* __restrict__ opacity) {
    int i = blockIdx.x * blockDim.x + threadIdx.x;
    if (i >= NG) return;
    const float LOG2E = 1.4426950408889634f;
    float cx = 0.5f * W * (tanhf(xyz[2 * i]) + 1.0f);
    float cy = 0.5f * H * (tanhf(xyz[2 * i + 1]) + 1.0f);
    float L0 = chol[3 * i] + 0.5f;
    float L1 = chol[3 * i + 1];
    float L2 = chol[3 * i + 2] + 0.5f;
    float cxx = L0 * L0;
    float cxy = L0 * L1;
    float cyy = L1 * L1 + L2 * L2;
    float det = cxx * cyy - cxy * cxy;
    float inv = 1.0f / det;
    float ha = 0.5f * cyy * inv * LOG2E;   // pre-scaled: sigma' = log2e * sigma
    float b  = -cxy * inv * LOG2E;
    float hc = 0.5f * cxx * inv * LOG2E;
    float op = opacity[i];
    float T = logf(255.0f * op) + 0.05f;   // sigma bound where alpha >= 1/255 (+margin)

    int tx0 = 15, tx1 = 0, ty0 = 15, ty1 = 0;  // empty range by default
    if (det > 0.0f && op > 0.0f && T > 0.0f) {
        float rx = sqrtf(2.0f * T * cxx) + 1.0f;
        float ry = sqrtf(2.0f * T * cyy) + 1.0f;
        float xlo = cx - rx, xhi = cx + rx;
        float ylo = cy - ry, yhi = cy + ry;
        if (xhi >= 0.0f && xlo <= (float)(W - 1) && yhi >= 0.0f && ylo <= (float)(H - 1)) {
            tx0 = max(0, (int)floorf(xlo * (1.0f / TS)));
            tx1 = min(TX - 1, (int)floorf(xhi * (1.0f / TS)));
            ty0 = max(0, (int)floorf(ylo * (1.0f / TS)));
            ty1 = min(TY - 1, (int)floorf(yhi * (1.0f / TS)));
        }
    }
    g_rng[i]  = tx0 | (tx1 << 4) | (ty0 << 8) | (ty1 << 12);
    g_parA[i] = make_float4(cx, cy, ha, b);
    g_parB[i] = make_float4(hc, log2f(op), colors[3 * i], colors[3 * i + 1]);
    g_parC[i] = colors[3 * i + 2];
}

// One block per tile row: compact gids overlapping this row, gid-sorted (deterministic).
__global__ __launch_bounds__(256) void row_bin_kernel() {
    const int row = blockIdx.x;
    const int tid = threadIdx.x, lane = tid & 31, wid = tid >> 5;
    __shared__ int wcnt[8];
    int outpos = 0;
    int* rl = g_rowlist + row * NG;
    for (int base = 0; base < NG; base += 256) {
        int i = base + tid;
        int rng = (i < NG) ? g_rng[i] : 0x0F00;  // ty0=15, ty1=0 -> never passes
        int y0 = (rng >> 8) & 15, y1 = (rng >> 12) & 15;
        bool pass = (y0 <= row) && (row <= y1);
        unsigned ball = __ballot_sync(0xffffffffu, pass);
        if (lane == 0) wcnt[wid] = __popc(ball);
        __syncthreads();
        int off = outpos, cnt = 0;
        #pragma unroll
        for (int k = 0; k < 8; k++) { int c = wcnt[k]; if (k < wid) off += c; cnt += c; }
        if (pass) {
            int pos = off + __popc(ball & ((1u << lane) - 1u));
            rl[pos] = i | ((rng & 15) << 20) | (((rng >> 4) & 15) << 24);
        }
        outpos += cnt;
        __syncthreads();
    }
    if (tid == 0) g_rowcnt[row] = outpos;
}

__global__ __launch_bounds__(256) void render_kernel(
    const float* __restrict__ scale_f,
    const float* __restrict__ shift_f,
    float* __restrict__ out) {
    __shared__ float4 sA[256];
    __shared__ float4 sB[256];
    __shared__ float  sC[256];
    __shared__ int    wcnt[8];

    const int tid = threadIdx.x, lane = tid & 31, wid = tid >> 5;
    const int bx = blockIdx.x, row = blockIdx.y;
    const int lx = tid & 15, ly = tid >> 4;
    const int px = bx * TS + lx, py = row * TS + ly;
    const float fpx = (float)px, fpy = (float)py;

    const int rcnt = g_rowcnt[row];
    const int* rl = g_rowlist + row * NG;

    float accR = 0.0f, accG = 0.0f, accB = 0.0f;

    for (int base = 0; base < rcnt; base += 256) {
        int i = base + tid;
        int e = (i < rcnt) ? rl[i] : (15 << 20);  // tx0=15,tx1=0 -> fails
        int t0 = (e >> 20) & 15, t1 = (e >> 24) & 15;
        bool pass = (t0 <= bx) && (bx <= t1);
        unsigned ball = __ballot_sync(0xffffffffu, pass);
        if (lane == 0) wcnt[wid] = __popc(ball);
        __syncthreads();
        int off = 0, cnt = 0;
        #pragma unroll
        for (int k = 0; k < 8; k++) { int c = wcnt[k]; if (k < wid) off += c; cnt += c; }
        if (pass) {
            int pos = off + __popc(ball & ((1u << lane) - 1u));
            int g = e & 0xFFFF;
            sA[pos] = g_parA[g];
            sB[pos] = g_parB[g];
            sC[pos] = g_parC[g];
        }
        __syncthreads();

        #pragma unroll 2
        for (int j = 0; j < cnt; j++) {
            float4 A = sA[j];
            float4 B = sB[j];
            float dx = A.x - fpx;
            float dy = A.y - fpy;
            // sigma' = log2e * sigma  (conic pre-scaled)
            float sig = fmaf(A.z * dx, dx, fmaf(B.x * dy, dy, A.w * (dx * dy)));
            float k2 = B.y - sig;  // log2(op) - sigma'
            float alpha;
            asm("ex2.approx.f32 %0, %1;" : "=f"(alpha) : "f"(k2));
            float wgt = ((sig >= 0.0f) && (alpha >= (1.0f / 255.0f)))
                            ? fminf(alpha, 0.999f) : 0.0f;
            accR = fmaf(wgt, B.z, accR);
            accG = fmaf(wgt, B.w, accG);
            accB = fmaf(wgt, sC[j], accB);
        }
        __syncthreads();
    }

    float s = scale_f[0];
    float sh = shift_f[0];
    int idx = py * W + px;
    out[0 * (H * W) + idx] = fmaf(accR, s, sh);
    out[1 * (H * W) + idx] = fmaf(accG, s, sh);
    out[2 * (H * W) + idx] = fmaf(accB, s, sh);
}

extern "C" void kernel_launch(void* const* d_in, const int* in_sizes, int n_in,
                              void* d_out, int out_size) {
    const float* xyz     = (const float*)d_in[0];
    const float* chol    = (const float*)d_in[1];
    const float* colors  = (const float*)d_in[2];
    const float* opacity = (const float*)d_in[3];
    const float* scale_f = (const float*)d_in[4];
    const float* shift_f = (const float*)d_in[5];
    float* out = (float*)d_out;

    prep_kernel<<<(NG + 255) / 256, 256>>>(xyz, chol, colors, opacity);
    row_bin_kernel<<<TY, 256>>>();
    render_kernel<<<dim3(TX, TY), 256>>>(scale_f, shift_f, out);
}

// round 3
// speedup vs baseline: 1.6199x; 1.3927x over previous
#include <cuda_runtime.h>
#include <cuda_bf16.h>

#define NG 10000
#define W 256
#define H 256
#define TS 16        // tile size (px)
#define TX 16        // tiles per row
#define TY 16        // tile rows
#define SEGS 8
#define SEGN (NG / SEGS)   // 1250
#define SEGCAP SEGN

// Static device scratch
static __device__ float4 g_parA[NG];                 // cx, cy, ha*log2e, b*log2e
static __device__ float4 g_parB[NG];                 // hc*log2e, log2(op), colR, colG
static __device__ float  g_parC[NG];                 // colB
static __device__ int    g_list[TY * SEGS * SEGCAP]; // entry: gid | tx0<<20 | tx1<<24
static __device__ int    g_cnt[TY * SEGS];

// Fused prep + per-row binning. Grid: (SEGS, TY). Each block preps its segment's
// gaussians (math duplicated across the 16 row-blocks — cheap) and compacts the
// ones overlapping its tile row, in deterministic gid order.
__global__ __launch_bounds__(256) void bin_kernel(
    const float* __restrict__ xyz,
    const float* __restrict__ chol,
    const float* __restrict__ colors,
    const float* __restrict__ opacity) {
    const int seg = blockIdx.x, row = blockIdx.y;
    const int tid = threadIdx.x, lane = tid & 31, wid = tid >> 5;
    __shared__ int wcnt[8];
    const int segBase = seg * SEGN;
    const int segEnd  = segBase + SEGN;
    int* rl = g_list + (row * SEGS + seg) * SEGCAP;
    int outpos = 0;
    const float LOG2E = 1.4426950408889634f;

    for (int it = 0; it < (SEGN + 255) / 256; it++) {
        int i = segBase + it * 256 + tid;
        bool pass = false;
        int tx0 = 0, tx1 = 0;
        if (i < segEnd) {
            float cx = 0.5f * W * (tanhf(xyz[2 * i]) + 1.0f);
            float cy = 0.5f * H * (tanhf(xyz[2 * i + 1]) + 1.0f);
            float L0 = chol[3 * i] + 0.5f;
            float L1 = chol[3 * i + 1];
            float L2 = chol[3 * i + 2] + 0.5f;
            float cxx = L0 * L0;
            float cxy = L0 * L1;
            float cyy = L1 * L1 + L2 * L2;
            float det = cxx * cyy - cxy * cxy;
            float inv = 1.0f / det;
            float op = opacity[i];
            float T = __logf(255.0f * op) + 0.05f;

            int ty0 = 1, ty1 = 0;
            if (det > 0.0f && op > 0.0f && T > 0.0f) {
                float rx = sqrtf(2.0f * T * cxx) + 1.0f;
                float ry = sqrtf(2.0f * T * cyy) + 1.0f;
                float xlo = cx - rx, xhi = cx + rx;
                float ylo = cy - ry, yhi = cy + ry;
                if (xhi >= 0.0f && xlo <= (float)(W - 1) &&
                    yhi >= 0.0f && ylo <= (float)(H - 1)) {
                    tx0 = max(0, (int)floorf(xlo * (1.0f / TS)));
                    tx1 = min(TX - 1, (int)floorf(xhi * (1.0f / TS)));
                    ty0 = max(0, (int)floorf(ylo * (1.0f / TS)));
                    ty1 = min(TY - 1, (int)floorf(yhi * (1.0f / TS)));
                }
            }
            pass = (ty0 <= row) && (row <= ty1);
            if (row == 0) {  // one row-block publishes shared params
                g_parA[i] = make_float4(cx, cy, 0.5f * cyy * inv * LOG2E,
                                        -cxy * inv * LOG2E);
                g_parB[i] = make_float4(0.5f * cxx * inv * LOG2E, __log2f(op),
                                        colors[3 * i], colors[3 * i + 1]);
                g_parC[i] = colors[3 * i + 2];
            }
        }
        unsigned ball = __ballot_sync(0xffffffffu, pass);
        if (lane == 0) wcnt[wid] = __popc(ball);
        __syncthreads();
        int off = outpos, cnt = 0;
        #pragma unroll
        for (int k = 0; k < 8; k++) { int c = wcnt[k]; if (k < wid) off += c; cnt += c; }
        if (pass) {
            int pos = off + __popc(ball & ((1u << lane) - 1u));
            rl[pos] = i | (tx0 << 20) | (tx1 << 24);
        }
        outpos += cnt;
        __syncthreads();
    }
    if (tid == 0) g_cnt[row * SEGS + seg] = outpos;
}

__global__ __launch_bounds__(256) void render_kernel(
    const float* __restrict__ scale_f,
    const float* __restrict__ shift_f,
    float* __restrict__ out) {
    __shared__ float4 sA[256];
    __shared__ float4 sB[256];
    __shared__ float  sC[256];
    __shared__ int    wcnt[8];

    const int tid = threadIdx.x, lane = tid & 31, wid = tid >> 5;
    const int bx = blockIdx.x, row = blockIdx.y;
    const int px = bx * TS + (tid & 15), py = row * TS + (tid >> 4);
    const float fpx = (float)px, fpy = (float)py;

    float accR = 0.0f, accG = 0.0f, accB = 0.0f;

    for (int seg = 0; seg < SEGS; seg++) {
        const int cnt_s = g_cnt[row * SEGS + seg];
        const int* rl = g_list + (row * SEGS + seg) * SEGCAP;
        for (int base = 0; base < cnt_s; base += 256) {
            int i = base + tid;
            int e = (i < cnt_s) ? rl[i] : (15 << 20);  // tx0=15,tx1=0 -> fails
            int t0 = (e >> 20) & 15, t1 = (e >> 24) & 15;
            bool pass = (t0 <= bx) && (bx <= t1);
            unsigned ball = __ballot_sync(0xffffffffu, pass);
            if (lane == 0) wcnt[wid] = __popc(ball);
            __syncthreads();
            int off = 0, cnt = 0;
            #pragma unroll
            for (int k = 0; k < 8; k++) { int c = wcnt[k]; if (k < wid) off += c; cnt += c; }
            if (pass) {
                int pos = off + __popc(ball & ((1u << lane) - 1u));
                int g = e & 0xFFFFF;
                sA[pos] = g_parA[g];
                sB[pos] = g_parB[g];
                sC[pos] = g_parC[g];
            }
            __syncthreads();

            #pragma unroll 2
            for (int j = 0; j < cnt; j++) {
                float4 A = sA[j];
                float4 B = sB[j];
                float dx = A.x - fpx;
                float dy = A.y - fpy;
                float sig = fmaf(A.z * dx, dx, fmaf(B.x * dy, dy, A.w * (dx * dy)));
                float k2 = B.y - sig;  // log2(op) - log2e*sigma
                float alpha;
                asm("ex2.approx.f32 %0, %1;" : "=f"(alpha) : "f"(k2));
                float wgt = ((sig >= 0.0f) && (alpha >= (1.0f / 255.0f)))
                                ? fminf(alpha, 0.999f) : 0.0f;
                accR = fmaf(wgt, B.z, accR);
                accG = fmaf(wgt, B.w, accG);
                accB = fmaf(wgt, sC[j], accB);
            }
            __syncthreads();
        }
    }

    float s = scale_f[0];
    float sh = shift_f[0];
    int idx = py * W + px;
    out[0 * (H * W) + idx] = fmaf(accR, s, sh);
    out[1 * (H * W) + idx] = fmaf(accG, s, sh);
    out[2 * (H * W) + idx] = fmaf(accB, s, sh);
}

extern "C" void kernel_launch(void* const* d_in, const int* in_sizes, int n_in,
                              void* d_out, int out_size) {
    const float* xyz     = (const float*)d_in[0];
    const float* chol    = (const float*)d_in[1];
    const float* colors  = (const float*)d_in[2];
    const float* opacity = (const float*)d_in[3];
    const float* scale_f = (const float*)d_in[4];
    const float* shift_f = (const float*)d_in[5];
    float* out = (float*)d_out;

    bin_kernel<<<dim3(SEGS, TY), 256>>>(xyz, chol, colors, opacity);
    render_kernel<<<dim3(TX, TY), 256>>>(scale_f, shift_f, out);
}

// round 5
// speedup vs baseline: 1.7844x; 1.1015x over previous
#include <cuda_runtime.h>
#include <cuda_bf16.h>

#define NG 10000
#define W 256
#define H 256
#define TS 16
#define TX 16
#define TY 16
#define SEGS 8
#define SEGN (NG / SEGS)   // 1250
#define CAP  SEGN          // per-(tile,seg) list capacity (worst case)
#define ZSPLIT 4           // render blocks per tile (each handles SEGS/ZSPLIT segs)

// Static device scratch (no dynamic allocation anywhere)
static __device__ float4 g_parA[NG];                    // cx, cy, ha*log2e, b*log2e
static __device__ float4 g_parB[NG];                    // hc*log2e, log2(op), colR, colG
static __device__ float  g_parC[NG];                    // colB
static __device__ int    g_tlist[TY * TX * SEGS * CAP]; // gid lists per (tile,seg)
static __device__ int    g_tcnt[TY * TX * SEGS];
static __device__ float  g_part[ZSPLIT][3 * H * W];     // partial accumulators

// Fused prep + exact per-tile binning. Grid (SEGS, TY).
// Each block preps its segment (math duplicated across the 16 row-blocks; cheap)
// and scatters gids into the 16 x-tile lists of its row via a deterministic
// 16-ballot block scan (gid-ascending order; no atomics -> bit-reproducible).
__global__ __launch_bounds__(256) void bin_kernel(
    const float* __restrict__ xyz,
    const float* __restrict__ chol,
    const float* __restrict__ colors,
    const float* __restrict__ opacity) {
    const int seg = blockIdx.x, row = blockIdx.y;
    const int tid = threadIdx.x, lane = tid & 31, wid = tid >> 5;
    __shared__ unsigned sball[TX][9];   // padded: avoid 8-way column conflicts
    __shared__ int sbase[TX];
    const int segBase = seg * SEGN;
    const float LOG2E = 1.4426950408889634f;
    const unsigned lmask = (1u << lane) - 1u;

    if (tid < TX) sbase[tid] = 0;
    __syncthreads();

    for (int it = 0; it < (SEGN + 255) / 256; it++) {
        int i = segBase + it * 256 + tid;
        bool pass = false;
        int t0 = 1, t1 = 0;
        if (i < segBase + SEGN) {
            float cx = 0.5f * W * (tanhf(xyz[2 * i]) + 1.0f);
            float cy = 0.5f * H * (tanhf(xyz[2 * i + 1]) + 1.0f);
            float L0 = chol[3 * i] + 0.5f;
            float L1 = chol[3 * i + 1];
            float L2 = chol[3 * i + 2] + 0.5f;
            float cxx = L0 * L0;
            float cxy = L0 * L1;
            float cyy = L1 * L1 + L2 * L2;
            float det = cxx * cyy - cxy * cxy;
            float inv = 1.0f / det;
            float op = opacity[i];
            float T = __logf(255.0f * op) + 0.05f;
            if (det > 0.0f && op > 0.0f && T > 0.0f) {
                float rx = sqrtf(2.0f * T * cxx) + 1.0f;
                float ry = sqrtf(2.0f * T * cyy) + 1.0f;
                float xlo = cx - rx, xhi = cx + rx;
                float ylo = cy - ry, yhi = cy + ry;
                if (xhi >= 0.0f && xlo <= (float)(W - 1) &&
                    yhi >= 0.0f && ylo <= (float)(H - 1)) {
                    int ty0 = max(0, (int)floorf(ylo * (1.0f / TS)));
                    int ty1 = min(TY - 1, (int)floorf(yhi * (1.0f / TS)));
                    if (ty0 <= row && row <= ty1) {
                        t0 = max(0, (int)floorf(xlo * (1.0f / TS)));
                        t1 = min(TX - 1, (int)floorf(xhi * (1.0f / TS)));
                        pass = true;
                    }
                }
            }
            if (row == 0) {  // one row-block publishes shared params
                g_parA[i] = make_float4(cx, cy, 0.5f * cyy * inv * LOG2E,
                                        -cxy * inv * LOG2E);
                g_parB[i] = make_float4(0.5f * cxx * inv * LOG2E, __log2f(op),
                                        colors[3 * i], colors[3 * i + 1]);
                g_parC[i] = colors[3 * i + 2];
            }
        }
        #pragma unroll
        for (int tx = 0; tx < TX; tx++) {
            unsigned b = __ballot_sync(0xffffffffu, pass && (t0 <= tx) && (tx <= t1));
            if (lane == 0) sball[tx][wid] = b;
        }
        __syncthreads();
        if (pass) {
            for (int tx = t0; tx <= t1; tx++) {
                int pos = sbase[tx];
                #pragma unroll
                for (int k = 0; k < 8; k++)
                    if (k < wid) pos += __popc(sball[tx][k]);
                pos += __popc(sball[tx][wid] & lmask);
                g_tlist[((row * TX + tx) * SEGS + seg) * CAP + pos] = i;
            }
        }
        __syncthreads();
        if (tid < TX) {
            int s = 0;
            #pragma unroll
            for (int k = 0; k < 8; k++) s += __popc(sball[tid][k]);
            sbase[tid] += s;
        }
        __syncthreads();
    }
    if (tid < TX) g_tcnt[(row * TX + tid) * SEGS + seg] = sbase[tid];
}

// Dense render: grid (TX, TY, ZSPLIT). Each z handles SEGS/ZSPLIT segments and
// writes a partial RGB accumulator. No culling — lists are tile-exact.
__global__ __launch_bounds__(256) void render_kernel() {
    __shared__ float4 sA[256];
    __shared__ float4 sB[256];
    __shared__ float  sC[256];

    const int tid = threadIdx.x;
    const int bx = blockIdx.x, row = blockIdx.y, z = blockIdx.z;
    const int px = bx * TS + (tid & 15), py = row * TS + (tid >> 4);
    const float fpx = (float)px, fpy = (float)py;
    const int tileIdx = row * TX + bx;

    float accR = 0.0f, accG = 0.0f, accB = 0.0f;
    const int seg0 = z * (SEGS / ZSPLIT);

    for (int s = 0; s < SEGS / ZSPLIT; s++) {
        const int seg = seg0 + s;
        const int cnt = g_tcnt[tileIdx * SEGS + seg];
        const int* lst = g_tlist + (tileIdx * SEGS + seg) * CAP;
        for (int base = 0; base < cnt; base += 256) {
            int i = base + tid;
            if (i < cnt) {
                int g = lst[i];
                sA[tid] = g_parA[g];
                sB[tid] = g_parB[g];
                sC[tid] = g_parC[g];
            }
            __syncthreads();
            int m = min(256, cnt - base);
            for (int j = 0; j < m; j++) {
                float4 A = sA[j];
                float4 B = sB[j];
                float dx = A.x - fpx;
                float dy = A.y - fpy;
                float sig = fmaf(A.z * dx, dx, fmaf(B.x * dy, dy, A.w * (dx * dy)));
                float k2 = B.y - sig;  // log2(op) - log2e*sigma
                float alpha;
                asm("ex2.approx.f32 %0, %1;" : "=f"(alpha) : "f"(k2));
                float wgt = ((sig >= 0.0f) && (alpha >= (1.0f / 255.0f)))
                                ? fminf(alpha, 0.999f) : 0.0f;
                accR = fmaf(wgt, B.z, accR);
                accG = fmaf(wgt, B.w, accG);
                accB = fmaf(wgt, sC[j], accB);
            }
            __syncthreads();
        }
    }

    int idx = py * W + px;
    g_part[z][0 * (H * W) + idx] = accR;
    g_part[z][1 * (H * W) + idx] = accG;
    g_part[z][2 * (H * W) + idx] = accB;
}

// Deterministic fixed-order reduction of partials + scale/shift.
__global__ __launch_bounds__(256) void finish_kernel(
    const float* __restrict__ scale_f,
    const float* __restrict__ shift_f,
    float* __restrict__ out) {
    int t = blockIdx.x * blockDim.x + threadIdx.x;  // float4 index
    const int n4 = 3 * H * W / 4;                   // 49152
    if (t >= n4) return;
    float s = scale_f[0], sh = shift_f[0];
    const float4* p0 = (const float4*)g_part[0];
    const float4* p1 = (const float4*)g_part[1];
    const float4* p2 = (const float4*)g_part[2];
    const float4* p3 = (const float4*)g_part[3];
    float4 a = p0[t], b = p1[t], c = p2[t], d = p3[t];
    float4 r;
    r.x = fmaf(((a.x + b.x) + (c.x + d.x)), s, sh);
    r.y = fmaf(((a.y + b.y) + (c.y + d.y)), s, sh);
    r.z = fmaf(((a.z + b.z) + (c.z + d.z)), s, sh);
    r.w = fmaf(((a.w + b.w) + (c.w + d.w)), s, sh);
    ((float4*)out)[t] = r;
}

extern "C" void kernel_launch(void* const* d_in, const int* in_sizes, int n_in,
                              void* d_out, int out_size) {
    const float* xyz     = (const float*)d_in[0];
    const float* chol    = (const float*)d_in[1];
    const float* colors  = (const float*)d_in[2];
    const float* opacity = (const float*)d_in[3];
    const float* scale_f = (const float*)d_in[4];
    const float* shift_f = (const float*)d_in[5];
    float* out = (float*)d_out;

    bin_kernel<<<dim3(SEGS, TY), 256>>>(xyz, chol, colors, opacity);
    render_kernel<<<dim3(TX, TY, ZSPLIT), 256>>>();
    finish_kernel<<<(3 * H * W / 4 + 255) / 256, 256>>>(scale_f, shift_f, out);
}